// round 6
// baseline (speedup 1.0000x reference)
#include <cuda_runtime.h>
#include <cuda_bf16.h>

#define S     32768
#define L     64
#define D_DIM 1024
#define BCH   256     // backtrack chunks
#define BB    128     // steps per backtrack chunk
#define NEGBIG -3.4e38f

// ---------------- device scratch (no runtime allocation) ----------------
__device__ __align__(16) float         g_E[(size_t)S * L];     // emissions, 8 MB
__device__ __align__(16) unsigned char g_bp[(size_t)S * L];    // backpointers, 2 MB
__device__ __align__(16) unsigned char g_comp[BCH * L];        // per-chunk composed maps
__device__ int    g_btag[BCH];
__device__ int    g_tags[S];
__device__ int    g_last_tag;
__device__ float  g_score;

// =======================================================================
// Emissions GEMM: E = feats @ W^T + b.  BM=128, BN=64(=L), BK=16, 256 thr.
// Dual accumulator sets (even/odd k-block) halve the sequential-sum
// rounding walk -> emissions within ~1.5e-6 of exact.
// =======================================================================
__global__ __launch_bounds__(256) void gemm_kernel(
    const float* __restrict__ feats, const float* __restrict__ Wm,
    const float* __restrict__ bias)
{
    __shared__ float As[16][132];
    __shared__ float Bs[16][68];
    const int tid = threadIdx.x;
    const int m0  = blockIdx.x * 128;
    const int ty  = tid >> 4;
    const int tx  = tid & 15;

    float accA[8][4], accB[8][4];
#pragma unroll
    for (int r = 0; r < 8; r++)
#pragma unroll
        for (int c = 0; c < 4; c++) { accA[r][c] = 0.f; accB[r][c] = 0.f; }

    for (int kb = 0; kb < D_DIM / 16; kb++) {
        const int k0 = kb * 16;
#pragma unroll
        for (int s = 0; s < 2; s++) {
            int l = tid + s * 256;
            int m = l >> 2, kq = l & 3;
            float4 f = *reinterpret_cast<const float4*>(
                &feats[(size_t)(m0 + m) * D_DIM + k0 + kq * 4]);
            As[kq * 4 + 0][m] = f.x; As[kq * 4 + 1][m] = f.y;
            As[kq * 4 + 2][m] = f.z; As[kq * 4 + 3][m] = f.w;
        }
        {
            int n = tid >> 2, kq = tid & 3;
            float4 f = *reinterpret_cast<const float4*>(
                &Wm[(size_t)n * D_DIM + k0 + kq * 4]);
            Bs[kq * 4 + 0][n] = f.x; Bs[kq * 4 + 1][n] = f.y;
            Bs[kq * 4 + 2][n] = f.z; Bs[kq * 4 + 3][n] = f.w;
        }
        __syncthreads();
        if (kb & 1) {
#pragma unroll
            for (int k = 0; k < 16; k++) {
                float4 a0 = *reinterpret_cast<const float4*>(&As[k][ty * 8]);
                float4 a1 = *reinterpret_cast<const float4*>(&As[k][ty * 8 + 4]);
                float4 bb = *reinterpret_cast<const float4*>(&Bs[k][tx * 4]);
                float am[8] = {a0.x, a0.y, a0.z, a0.w, a1.x, a1.y, a1.z, a1.w};
                float bn[4] = {bb.x, bb.y, bb.z, bb.w};
#pragma unroll
                for (int r = 0; r < 8; r++)
#pragma unroll
                    for (int c = 0; c < 4; c++) accB[r][c] += am[r] * bn[c];
            }
        } else {
#pragma unroll
            for (int k = 0; k < 16; k++) {
                float4 a0 = *reinterpret_cast<const float4*>(&As[k][ty * 8]);
                float4 a1 = *reinterpret_cast<const float4*>(&As[k][ty * 8 + 4]);
                float4 bb = *reinterpret_cast<const float4*>(&Bs[k][tx * 4]);
                float am[8] = {a0.x, a0.y, a0.z, a0.w, a1.x, a1.y, a1.z, a1.w};
                float bn[4] = {bb.x, bb.y, bb.z, bb.w};
#pragma unroll
                for (int r = 0; r < 8; r++)
#pragma unroll
                    for (int c = 0; c < 4; c++) accA[r][c] += am[r] * bn[c];
            }
        }
        __syncthreads();
    }
    float4 bv = *reinterpret_cast<const float4*>(&bias[tx * 4]);
#pragma unroll
    for (int r = 0; r < 8; r++) {
        float4 o;
        o.x = (accA[r][0] + accB[r][0]) + bv.x;
        o.y = (accA[r][1] + accB[r][1]) + bv.y;
        o.z = (accA[r][2] + accB[r][2]) + bv.z;
        o.w = (accA[r][3] + accB[r][3]) + bv.w;
        *reinterpret_cast<float4*>(
            &g_E[(size_t)(m0 + ty * 8 + r) * L + tx * 4]) = o;
    }
}

// =======================================================================
// One exact fp32 Viterbi step.  256 threads: j = tid>>2 owns state j,
// q = tid&3 covers preds i in [16q,16q+16).  Bit-exact replication of
// reference: cand = fl32(x_i + T[j,i]); max; FIRST-index argmax;
// x_new = fl32(e + max).
// =======================================================================
__device__ __forceinline__ void exact_step(int t, float e_j, int p, int j, int q,
                                           const float* __restrict__ Tr,
                                           float (*xs)[L])
{
    const float* xr = xs[p] + q * 16;
    float4 a = *reinterpret_cast<const float4*>(xr + 0);
    float4 b = *reinterpret_cast<const float4*>(xr + 4);
    float4 c = *reinterpret_cast<const float4*>(xr + 8);
    float4 d = *reinterpret_cast<const float4*>(xr + 12);
    float xv[16] = {a.x, a.y, a.z, a.w, b.x, b.y, b.z, b.w,
                    c.x, c.y, c.z, c.w, d.x, d.y, d.z, d.w};
    float v[16];
#pragma unroll
    for (int z = 0; z < 16; z++) v[z] = xv[z] + Tr[z];

    // pair-tree (val, idx); lower index wins ties at every level
    float bv1[8]; int bi1[8];
#pragma unroll
    for (int z = 0; z < 8; z++) {
        bool g = v[2 * z + 1] > v[2 * z];
        bv1[z] = g ? v[2 * z + 1] : v[2 * z];
        bi1[z] = g ? 2 * z + 1 : 2 * z;
    }
    float bv2[4]; int bi2[4];
#pragma unroll
    for (int z = 0; z < 4; z++) {
        bool g = bv1[2 * z + 1] > bv1[2 * z];
        bv2[z] = g ? bv1[2 * z + 1] : bv1[2 * z];
        bi2[z] = g ? bi1[2 * z + 1] : bi1[2 * z];
    }
    float bv3[2]; int bi3[2];
#pragma unroll
    for (int z = 0; z < 2; z++) {
        bool g = bv2[2 * z + 1] > bv2[2 * z];
        bv3[z] = g ? bv2[2 * z + 1] : bv2[2 * z];
        bi3[z] = g ? bi2[2 * z + 1] : bi2[2 * z];
    }
    bool gg = bv3[1] > bv3[0];
    float val = gg ? bv3[1] : bv3[0];
    int   idx = q * 16 + (gg ? bi3[1] : bi3[0]);

    // cross-q combine: 2 xor levels; all 4 lanes converge to (max, min idx)
    float ov = __shfl_xor_sync(0xffffffffu, val, 1);
    int   oi = __shfl_xor_sync(0xffffffffu, idx, 1);
    if (ov > val || (ov == val && oi < idx)) { val = ov; idx = oi; }
    ov = __shfl_xor_sync(0xffffffffu, val, 2);
    oi = __shfl_xor_sync(0xffffffffu, idx, 2);
    if (ov > val || (ov == val && oi < idx)) { val = ov; idx = oi; }

    if (q == 0) {
        xs[p ^ 1][j] = e_j + val;
        g_bp[(size_t)t * L + j] = (unsigned char)idx;
    }
    __syncthreads();
}

__global__ __launch_bounds__(256) void forward_exact(const float* __restrict__ T)
{
    __shared__ float xs[2][L];
    const int tid = threadIdx.x;
    const int j = tid >> 2, q = tid & 3;

    float Tr[16];
#pragma unroll
    for (int z = 0; z < 16; z += 4) {
        float4 f = *reinterpret_cast<const float4*>(&T[(size_t)j * L + q * 16 + z]);
        Tr[z] = f.x; Tr[z + 1] = f.y; Tr[z + 2] = f.z; Tr[z + 3] = f.w;
    }

    // init: v0[j] = fl32(T[j, START=0] + E[0, j])
    if (tid < L) xs[0][tid] = T[(size_t)tid * L + 0] + g_E[tid];
    __syncthreads();

    // emission pipeline: lane q of each 4-group holds E for substep q of a quad.
    float e_cur = g_E[(size_t)(1 + q) * L + j];   // quad t=1
    float e_nxt = g_E[(size_t)(5 + q) * L + j];   // quad t=5

    int p = 0;
    int t = 1;
    for (; t + 3 <= S - 1; t += 4) {
        float e_use = e_cur;
        e_cur = e_nxt;
        int tp = t + 8 + q;                 // prefetch quad t+8
        if (tp > S - 1) tp = S - 1;
        e_nxt = g_E[(size_t)tp * L + j];
#pragma unroll
        for (int u = 0; u < 4; u++) {
            float e_j = __shfl_sync(0xffffffffu, e_use, u, 4);
            exact_step(t + u, e_j, p, j, q, Tr, xs);
            p ^= 1;
        }
    }
    for (; t <= S - 1; t++) {               // 3 tail steps
        float e_j = g_E[(size_t)t * L + j];
        exact_step(t, e_j, p, j, q, Tr, xs);
        p ^= 1;
    }

    // final: fs = fl32(x + T[END=63, :]); score = max (fp32); first argmax
    if (tid < L) xs[p ^ 1][tid] = xs[p][tid] + T[63 * L + tid];
    __syncthreads();
    if (tid == 0) {
        float best = NEGBIG; int bi = 0;
#pragma unroll 8
        for (int i = 0; i < L; i++) {
            float v = xs[p ^ 1][i];
            if (v > best) { best = v; bi = i; }
        }
        g_last_tag = bi;
        g_score = best;
    }
}

// =======================================================================
// Backtrack phase 1: per-chunk composed backpointer maps.
// =======================================================================
__global__ __launch_bounds__(64) void btmap_kernel()
{
    __shared__ unsigned char bp[BB][L];
    const int c = blockIdx.x, tid = threadIdx.x;
    const uint4* src = reinterpret_cast<const uint4*>(g_bp + (size_t)c * BB * L);
    uint4* dst = reinterpret_cast<uint4*>(&bp[0][0]);
    for (int k = tid; k < BB * L / 16; k += 64) dst[k] = src[k];
    __syncthreads();
    const int ts = (c == 0) ? 1 : c * BB;
    const int te = (c + 1) * BB - 1;
    const int base = c * BB;
    int m = tid;
    for (int t = te; t >= ts; --t) m = bp[t - base][m];
    g_comp[c * L + tid] = (unsigned char)m;
}

// Backtrack phase 2: sequential chain over the 256 chunk maps.
__global__ __launch_bounds__(256) void chain_kernel()
{
    __shared__ unsigned char cmS[BCH * L];
    const int tid = threadIdx.x;
    const uint4* src = reinterpret_cast<const uint4*>(g_comp);
    uint4* dst = reinterpret_cast<uint4*>(cmS);
    for (int k = tid; k < BCH * L / 16; k += 256) dst[k] = src[k];
    __syncthreads();
    if (tid == 0) {
        int e = g_last_tag;
        for (int c = BCH - 1; c >= 1; --c) {
            g_btag[c] = e;
            e = cmS[c * L + e];
        }
        g_btag[0] = e;
        g_tags[0] = cmS[0 * L + e];
    }
}

// Backtrack phase 3: per-chunk tag writeout.
__global__ __launch_bounds__(64) void tagwrite_kernel()
{
    __shared__ unsigned char bp[BB][L];
    const int c = blockIdx.x, tid = threadIdx.x;
    const uint4* src = reinterpret_cast<const uint4*>(g_bp + (size_t)c * BB * L);
    uint4* dst = reinterpret_cast<uint4*>(&bp[0][0]);
    for (int k = tid; k < BB * L / 16; k += 64) dst[k] = src[k];
    __syncthreads();
    if (tid == 0) {
        const int ts = (c == 0) ? 1 : c * BB;
        const int te = (c + 1) * BB - 1;
        const int base = c * BB;
        int tag = g_btag[c];
        for (int t = te; t >= ts; --t) { g_tags[t] = tag; tag = bp[t - base][tag]; }
        if (c == 0) g_tags[0] = tag;
    }
}

// Output writeout, layout chosen by out_size.
__global__ void writeout_kernel(float* outf, int* outi, int out_size)
{
    const int idx = blockIdx.x * blockDim.x + threadIdx.x;
    if (out_size == 1) {
        if (idx == 0) outf[0] = g_score;
        return;
    }
    if (out_size == S) {
        if (idx < S) outi[idx] = g_tags[idx];
        return;
    }
    if (idx == 0) outf[0] = g_score;
    else if (idx < out_size && idx <= S) outf[idx] = (float)g_tags[idx - 1];
}

extern "C" void kernel_launch(void* const* d_in, const int* in_sizes, int n_in,
                              void* d_out, int out_size)
{
    const float* feats = (const float*)d_in[0];
    const float* W     = (const float*)d_in[1];
    const float* b     = (const float*)d_in[2];
    const float* T     = (const float*)d_in[3];

    gemm_kernel<<<S / 128, 256>>>(feats, W, b);
    forward_exact<<<1, 256>>>(T);
    btmap_kernel<<<BCH, 64>>>();
    chain_kernel<<<1, 256>>>();
    tagwrite_kernel<<<BCH, 64>>>();
    writeout_kernel<<<(S + 1 + 255) / 256 + 1, 256>>>((float*)d_out, (int*)d_out, out_size);
}

// round 9
// speedup vs baseline: 1.4953x; 1.4953x over previous
#include <cuda_runtime.h>
#include <cuda_bf16.h>

#define S     32768
#define L     64
#define D_DIM 1024
#define BCH   256     // backtrack chunks
#define BB    128     // steps per backtrack chunk
#define TT    64      // timesteps per bp-recompute block
#define NEGBIG -3.4e38f

// ---------------- device scratch (no runtime allocation) ----------------
__device__ __align__(16) float         g_E[(size_t)S * L];     // emissions, 8 MB
__device__ __align__(16) float         g_X[(size_t)S * L];     // score history, 8 MB
__device__ __align__(16) unsigned char g_bp[(size_t)S * L];    // backpointers, 2 MB
__device__ __align__(16) unsigned char g_comp[BCH * L];
__device__ int    g_btag[BCH];
__device__ int    g_tags[S];
__device__ int    g_last_tag;
__device__ float  g_score;

// =======================================================================
// Emissions GEMM: E = feats @ W^T + b  (unchanged from R6 — passed).
// =======================================================================
__global__ __launch_bounds__(256) void gemm_kernel(
    const float* __restrict__ feats, const float* __restrict__ Wm,
    const float* __restrict__ bias)
{
    __shared__ float As[16][132];
    __shared__ float Bs[16][68];
    const int tid = threadIdx.x;
    const int m0  = blockIdx.x * 128;
    const int ty  = tid >> 4;
    const int tx  = tid & 15;

    float accA[8][4], accB[8][4];
#pragma unroll
    for (int r = 0; r < 8; r++)
#pragma unroll
        for (int c = 0; c < 4; c++) { accA[r][c] = 0.f; accB[r][c] = 0.f; }

    for (int kb = 0; kb < D_DIM / 16; kb++) {
        const int k0 = kb * 16;
#pragma unroll
        for (int s = 0; s < 2; s++) {
            int l = tid + s * 256;
            int m = l >> 2, kq = l & 3;
            float4 f = *reinterpret_cast<const float4*>(
                &feats[(size_t)(m0 + m) * D_DIM + k0 + kq * 4]);
            As[kq * 4 + 0][m] = f.x; As[kq * 4 + 1][m] = f.y;
            As[kq * 4 + 2][m] = f.z; As[kq * 4 + 3][m] = f.w;
        }
        {
            int n = tid >> 2, kq = tid & 3;
            float4 f = *reinterpret_cast<const float4*>(
                &Wm[(size_t)n * D_DIM + k0 + kq * 4]);
            Bs[kq * 4 + 0][n] = f.x; Bs[kq * 4 + 1][n] = f.y;
            Bs[kq * 4 + 2][n] = f.z; Bs[kq * 4 + 3][n] = f.w;
        }
        __syncthreads();
        if (kb & 1) {
#pragma unroll
            for (int k = 0; k < 16; k++) {
                float4 a0 = *reinterpret_cast<const float4*>(&As[k][ty * 8]);
                float4 a1 = *reinterpret_cast<const float4*>(&As[k][ty * 8 + 4]);
                float4 bb = *reinterpret_cast<const float4*>(&Bs[k][tx * 4]);
                float am[8] = {a0.x, a0.y, a0.z, a0.w, a1.x, a1.y, a1.z, a1.w};
                float bn[4] = {bb.x, bb.y, bb.z, bb.w};
#pragma unroll
                for (int r = 0; r < 8; r++)
#pragma unroll
                    for (int c = 0; c < 4; c++) accB[r][c] += am[r] * bn[c];
            }
        } else {
#pragma unroll
            for (int k = 0; k < 16; k++) {
                float4 a0 = *reinterpret_cast<const float4*>(&As[k][ty * 8]);
                float4 a1 = *reinterpret_cast<const float4*>(&As[k][ty * 8 + 4]);
                float4 bb = *reinterpret_cast<const float4*>(&Bs[k][tx * 4]);
                float am[8] = {a0.x, a0.y, a0.z, a0.w, a1.x, a1.y, a1.z, a1.w};
                float bn[4] = {bb.x, bb.y, bb.z, bb.w};
#pragma unroll
                for (int r = 0; r < 8; r++)
#pragma unroll
                    for (int c = 0; c < 4; c++) accA[r][c] += am[r] * bn[c];
            }
        }
        __syncthreads();
    }
    float4 bv = *reinterpret_cast<const float4*>(&bias[tx * 4]);
#pragma unroll
    for (int r = 0; r < 8; r++) {
        float4 o;
        o.x = (accA[r][0] + accB[r][0]) + bv.x;
        o.y = (accA[r][1] + accB[r][1]) + bv.y;
        o.z = (accA[r][2] + accB[r][2]) + bv.z;
        o.w = (accA[r][3] + accB[r][3]) + bv.w;
        *reinterpret_cast<float4*>(
            &g_E[(size_t)(m0 + ty * 8 + r) * L + tx * 4]) = o;
    }
}

// =======================================================================
// Max-only exact forward.  128 threads: j = tid>>1, q = tid&1 covers
// preds [32q, 32q+32).  max is exact -> order-free; x history bit-exact.
// RP = read buffer parity (compile-time).
// =======================================================================
template <int RP>
__device__ __forceinline__ void vstep(int t, float e_j, int j, int q,
                                      const float* __restrict__ Tr,
                                      float (*xs)[L])
{
    const float* xr = xs[RP] + q * 32;
    float pm[8];
#pragma unroll
    for (int g = 0; g < 8; g++) {
        float4 xv = reinterpret_cast<const float4*>(xr)[g];
        float c0 = xv.x + Tr[4 * g + 0];
        float c1 = xv.y + Tr[4 * g + 1];
        float c2 = xv.z + Tr[4 * g + 2];
        float c3 = xv.w + Tr[4 * g + 3];
        pm[g] = fmaxf(fmaxf(c0, c1), fmaxf(c2, c3));
    }
    float m = fmaxf(fmaxf(fmaxf(pm[0], pm[1]), fmaxf(pm[2], pm[3])),
                    fmaxf(fmaxf(pm[4], pm[5]), fmaxf(pm[6], pm[7])));
    m = fmaxf(m, __shfl_xor_sync(0xffffffffu, m, 1));
    if (q == 0) {
        float xn = e_j + m;
        xs[RP ^ 1][j] = xn;
        g_X[(size_t)t * L + j] = xn;     // history for parallel bp recompute
    }
    __syncthreads();
}

__global__ __launch_bounds__(128, 1) void forward_kernel2(const float* __restrict__ T)
{
    __shared__ float xs[2][L];
    const int tid = threadIdx.x;
    const int j = tid >> 1, q = tid & 1;

    float Tr[32];
#pragma unroll
    for (int z = 0; z < 32; z += 4) {
        float4 f = *reinterpret_cast<const float4*>(&T[(size_t)j * L + q * 32 + z]);
        Tr[z] = f.x; Tr[z + 1] = f.y; Tr[z + 2] = f.z; Tr[z + 3] = f.w;
    }
    if (tid < L) {
        float x0 = T[(size_t)tid * L + 0] + g_E[tid];   // v0 = T[:,START] + E[0]
        xs[0][tid] = x0;
        g_X[tid] = x0;
    }
    __syncthreads();

    // emission prefetch pipeline, depth 4 (each thread fetches its own j)
    float e0 = g_E[(size_t)1 * L + j];
    float e1 = g_E[(size_t)2 * L + j];
    float e2 = g_E[(size_t)3 * L + j];
    float e3 = g_E[(size_t)4 * L + j];

    int t = 1;
#pragma unroll 1
    for (; t + 3 <= S - 1; t += 4) {       // loop top: t % 4 == 1, x in buf 0
        vstep<0>(t + 0, e0, j, q, Tr, xs);
        { int tp = t + 4; if (tp > S - 1) tp = S - 1; e0 = g_E[(size_t)tp * L + j]; }
        vstep<1>(t + 1, e1, j, q, Tr, xs);
        { int tp = t + 5; if (tp > S - 1) tp = S - 1; e1 = g_E[(size_t)tp * L + j]; }
        vstep<0>(t + 2, e2, j, q, Tr, xs);
        { int tp = t + 6; if (tp > S - 1) tp = S - 1; e2 = g_E[(size_t)tp * L + j]; }
        vstep<1>(t + 3, e3, j, q, Tr, xs);
        { int tp = t + 7; if (tp > S - 1) tp = S - 1; e3 = g_E[(size_t)tp * L + j]; }
    }
    // tail: t = 32765,32766,32767 (parities 1,0,1 -> read 0,1,0)
    vstep<0>(t + 0, e0, j, q, Tr, xs);
    vstep<1>(t + 1, e1, j, q, Tr, xs);
    vstep<0>(t + 2, e2, j, q, Tr, xs);
    // final x lives in xs[1]

    if (tid < L) xs[0][tid] = xs[1][tid] + T[63 * L + tid];   // + T[END]
    __syncthreads();
    if (tid == 0) {
        float best = NEGBIG; int bi = 0;
#pragma unroll 8
        for (int i = 0; i < L; i++) {
            float v = xs[0][i];
            if (v > best) { best = v; bi = i; }   // first-max
        }
        g_last_tag = bi;
        g_score = best;
    }
}

// =======================================================================
// Parallel backpointer recompute: bp[t][j] = first argmax_i fl(x[t-1][i]
// + T[j][i]).  Candidates are bit-identical to the forward recurrence, so
// equality-vs-max with ascending-first tie-break reproduces jnp.argmax.
// =======================================================================
__global__ __launch_bounds__(256) void bprec_kernel(const float* __restrict__ T)
{
    __shared__ float xsh[TT][L];     // x rows t0-1 .. t0+TT-2  (16 KB)
    const int tid = threadIdx.x;
    const int t0  = 1 + blockIdx.x * TT;
    {
        const float4* src = reinterpret_cast<const float4*>(&g_X[(size_t)(t0 - 1) * L]);
        float4* dst = reinterpret_cast<float4*>(&xsh[0][0]);
        for (int k = tid; k < TT * L / 4; k += 256) dst[k] = src[k];
    }
    __syncthreads();

    const int j  = tid & 63;
    const int tt = tid >> 6;
    float Tr[64];
#pragma unroll
    for (int z = 0; z < 64; z += 4) {
        float4 f = *reinterpret_cast<const float4*>(&T[(size_t)j * L + z]);
        Tr[z] = f.x; Tr[z + 1] = f.y; Tr[z + 2] = f.z; Tr[z + 3] = f.w;
    }

#pragma unroll 1
    for (int k = 0; k < TT / 4; k++) {
        const int t = t0 + tt + 4 * k;
        if (t > S - 1) continue;
        const float* xr = xsh[t - t0];
        // pass 1: exact max
        float pm[16];
#pragma unroll
        for (int g = 0; g < 16; g++) {
            float4 xv = reinterpret_cast<const float4*>(xr)[g];
            float c0 = xv.x + Tr[4 * g + 0];
            float c1 = xv.y + Tr[4 * g + 1];
            float c2 = xv.z + Tr[4 * g + 2];
            float c3 = xv.w + Tr[4 * g + 3];
            pm[g] = fmaxf(fmaxf(c0, c1), fmaxf(c2, c3));
        }
        float m = fmaxf(fmaxf(fmaxf(pm[0], pm[1]), fmaxf(pm[2], pm[3])),
                        fmaxf(fmaxf(pm[4], pm[5]), fmaxf(pm[6], pm[7])));
        m = fmaxf(m, fmaxf(fmaxf(fmaxf(pm[8], pm[9]), fmaxf(pm[10], pm[11])),
                           fmaxf(fmaxf(pm[12], pm[13]), fmaxf(pm[14], pm[15]))));
        // pass 2: first (smallest) index achieving m — descending so last write wins
        int idx = 0;
#pragma unroll
        for (int i = 63; i >= 0; --i) {
            float cnd = xr[i] + Tr[i];
            if (cnd == m) idx = i;
        }
        g_bp[(size_t)t * L + j] = (unsigned char)idx;
    }
}

// =======================================================================
// Backtrack (unchanged from R6 — passed).
// =======================================================================
__global__ __launch_bounds__(64) void btmap_kernel()
{
    __shared__ unsigned char bp[BB][L];
    const int c = blockIdx.x, tid = threadIdx.x;
    const uint4* src = reinterpret_cast<const uint4*>(g_bp + (size_t)c * BB * L);
    uint4* dst = reinterpret_cast<uint4*>(&bp[0][0]);
    for (int k = tid; k < BB * L / 16; k += 64) dst[k] = src[k];
    __syncthreads();
    const int ts = (c == 0) ? 1 : c * BB;
    const int te = (c + 1) * BB - 1;
    const int base = c * BB;
    int m = tid;
    for (int t = te; t >= ts; --t) m = bp[t - base][m];
    g_comp[c * L + tid] = (unsigned char)m;
}

__global__ __launch_bounds__(256) void chain_kernel()
{
    __shared__ unsigned char cmS[BCH * L];
    const int tid = threadIdx.x;
    const uint4* src = reinterpret_cast<const uint4*>(g_comp);
    uint4* dst = reinterpret_cast<uint4*>(cmS);
    for (int k = tid; k < BCH * L / 16; k += 256) dst[k] = src[k];
    __syncthreads();
    if (tid == 0) {
        int e = g_last_tag;
        for (int c = BCH - 1; c >= 1; --c) {
            g_btag[c] = e;
            e = cmS[c * L + e];
        }
        g_btag[0] = e;
        g_tags[0] = cmS[0 * L + e];
    }
}

__global__ __launch_bounds__(64) void tagwrite_kernel()
{
    __shared__ unsigned char bp[BB][L];
    const int c = blockIdx.x, tid = threadIdx.x;
    const uint4* src = reinterpret_cast<const uint4*>(g_bp + (size_t)c * BB * L);
    uint4* dst = reinterpret_cast<uint4*>(&bp[0][0]);
    for (int k = tid; k < BB * L / 16; k += 64) dst[k] = src[k];
    __syncthreads();
    if (tid == 0) {
        const int ts = (c == 0) ? 1 : c * BB;
        const int te = (c + 1) * BB - 1;
        const int base = c * BB;
        int tag = g_btag[c];
        for (int t = te; t >= ts; --t) { g_tags[t] = tag; tag = bp[t - base][tag]; }
        if (c == 0) g_tags[0] = tag;
    }
}

__global__ void writeout_kernel(float* outf, int* outi, int out_size)
{
    const int idx = blockIdx.x * blockDim.x + threadIdx.x;
    if (out_size == 1) {
        if (idx == 0) outf[0] = g_score;
        return;
    }
    if (out_size == S) {
        if (idx < S) outi[idx] = g_tags[idx];
        return;
    }
    if (idx == 0) outf[0] = g_score;
    else if (idx < out_size && idx <= S) outf[idx] = (float)g_tags[idx - 1];
}

extern "C" void kernel_launch(void* const* d_in, const int* in_sizes, int n_in,
                              void* d_out, int out_size)
{
    const float* feats = (const float*)d_in[0];
    const float* W     = (const float*)d_in[1];
    const float* b     = (const float*)d_in[2];
    const float* T     = (const float*)d_in[3];

    gemm_kernel<<<S / 128, 256>>>(feats, W, b);
    forward_kernel2<<<1, 128>>>(T);
    bprec_kernel<<<(S - 1 + TT - 1) / TT, 256>>>(T);
    btmap_kernel<<<BCH, 64>>>();
    chain_kernel<<<1, 256>>>();
    tagwrite_kernel<<<BCH, 64>>>();
    writeout_kernel<<<(S + 1 + 255) / 256 + 1, 256>>>((float*)d_out, (int*)d_out, out_size);
}